// round 13
// baseline (speedup 1.0000x reference)
#include <cuda_runtime.h>
#include <cuda_fp16.h>
#include <cstdint>

#define NB 16
#define CIN 256
#define LL 300
#define VV 25
#define PP 3
#define COUT 256
#define NCOL 120000
#define CPN 7500
#define KDIM 768
#define NKC 24            // K chunks of 32

#define BN 100            // 4 LN-frame groups per CTA
#define BALLS 104         // halves per B_all row (208 B, 16B-aligned rows)
#define XTS 136           // halves per XT row (272 B: 16B-aligned, LDSM conflict-free)
#define ASTG 8192         // A halves per chunk
#define NSTAGE 4
#define CS_STRIDE 261
#define BALL_BYTES (KDIM * BALLS * 2)          // 159744
#define XT_BYTES (256 * XTS * 2)               // 69632
#define GEMM_SMEM (BALL_BYTES + XT_BYTES)      // 229376

__device__ __half g_Afrag[COUT * KDIM];         // fp16 fragment-ordered Wall
__device__ uint32_t g_AwFrag2[PP * 4 * 2 * 32 * 2];  // [p][nt][k16][lane][j]
__device__ float g_bias2[COUT * VV];

__device__ __forceinline__ void cp16(uint32_t dst, const void* src) {
    asm volatile("cp.async.cg.shared.global [%0], [%1], 16;" :: "r"(dst), "l"(src));
}
__device__ __forceinline__ uint32_t smem_u32(const void* p) {
    uint32_t a;
    asm("{ .reg .u64 t; cvta.to.shared.u64 t, %1; cvt.u32.u64 %0, t; }" : "=r"(a) : "l"(p));
    return a;
}
__device__ __forceinline__ void mma_f16(float* d, uint32_t a0, uint32_t a1, uint32_t a2,
                                        uint32_t a3, uint32_t b0, uint32_t b1) {
    asm volatile(
        "mma.sync.aligned.m16n8k16.row.col.f32.f16.f16.f32 "
        "{%0,%1,%2,%3}, {%4,%5,%6,%7}, {%8,%9}, {%0,%1,%2,%3};"
        : "+f"(d[0]), "+f"(d[1]), "+f"(d[2]), "+f"(d[3])
        : "r"(a0), "r"(a1), "r"(a2), "r"(a3), "r"(b0), "r"(b1));
}
#define LDSM_X4_T(r0, r1, r2, r3, addr) \
    asm volatile("ldmatrix.sync.aligned.m8n8.x4.trans.shared.b16 {%0,%1,%2,%3}, [%4];" \
                 : "=r"(r0), "=r"(r1), "=r"(r2), "=r"(r3) : "r"(addr))
#define LDSM_X4(r0, r1, r2, r3, addr) \
    asm volatile("ldmatrix.sync.aligned.m8n8.x4.shared.b16 {%0,%1,%2,%3}, [%4];" \
                 : "=r"(r0), "=r"(r1), "=r"(r2), "=r"(r3) : "r"(addr))

// ---------------- prep: fp16 A fragments, AwFrag2 (per-p B frags), bias2 -----------
__global__ __launch_bounds__(256) void prep_kernel(const float* __restrict__ A,
                                                   const float* __restrict__ conv_w,
                                                   const float* __restrict__ conv_b,
                                                   const float* __restrict__ ei) {
    int e = blockIdx.x * 256 + threadIdx.x;
    if (e < COUT * KDIM) {
        int r = e / KDIM;
        int k = e - r * KDIM;
        int p = k >> 8, ci = k & 255;
        float w = conv_w[((p << 8) + r) * CIN + ci];
        int wm = r >> 5, fm = (r >> 4) & 1, rr = r & 15;
        int kchunk = k >> 5, k16 = (k >> 4) & 1, kkk = k & 15;
        int reg = (rr >> 3) | ((kkk >> 3) << 1);
        int lane = ((rr & 7) << 2) | ((kkk & 7) >> 1);
        int hl = kkk & 1;
        size_t off = ((((size_t)(kchunk * 8 + wm) * 2 + k16) * 2 + fm) * 256)
                     + lane * 8 + reg * 2 + hl;
        g_Afrag[off] = __float2half_rn(w);
    }
    if (e < PP * 4 * 2 * 32 * 2) {
        // e = (((p*4 + nt)*2 + k16)*32 + lane)*2 + j
        int j = e & 1;
        int lane = (e >> 1) & 31;
        int k16 = (e >> 6) & 1;
        int nt = (e >> 7) & 3;
        int p = e >> 9;
        int grp = lane >> 2, tig = lane & 3;
        int w = nt * 8 + grp;
        int v = k16 * 16 + j * 8 + 2 * tig;
        float v0 = 0.f, v1 = 0.f;
        if (w < 25) {
            if (v < 25) {
                int a = (p * VV + v) * VV + w;
                v0 = A[a] * ei[a];
            }
            if (v + 1 < 25) {
                int a = (p * VV + v + 1) * VV + w;
                v1 = A[a] * ei[a];
            }
        }
        __half2 h2 = __floats2half2_rn(v0, v1);
        g_AwFrag2[e] = *(uint32_t*)&h2;
    }
    if (e < COUT * VV) {
        int c = e / VV, w = e - (e / VV) * VV;
        float s = 0.f;
        for (int p = 0; p < PP; ++p) {
            float b = conv_b[(p << 8) + c];
            for (int v = 0; v < VV; ++v) {
                int a = (p * VV + v) * VV + w;
                s += b * A[a] * ei[a];
            }
        }
        g_bias2[e] = s;
    }
}

// ---------------- fused mega-kernel: window sums + agg-MMA + GEMM + LN ------------
__global__ __launch_bounds__(512, 1) void gemm_kernel(const float* __restrict__ x,
                                                      const float* __restrict__ gamma,
                                                      const float* __restrict__ beta,
                                                      float* __restrict__ out) {
    extern __shared__ float dyns[];
    __half* Ball = (__half*)dyns;                         // [768][104]
    __half* XT = (__half*)((char*)dyns + BALL_BYTES);     // [256][136]; later A stages
    __shared__ float red[16][4];
    __shared__ float smean[4], srstd[4];

    const int tid = threadIdx.x;
    const int warp = tid >> 5;
    const int lane = tid & 31;
    const int wm = warp >> 1;
    const int wn = warp & 1;
    const int grp = lane >> 2;
    const int tig = lane & 3;
    const int fnc = wn ? 6 : 7;
    const int bx = blockIdx.x;
    const int n = bx / 75;
    const int loc0 = (bx % 75) * BN;
    const int mf0 = (bx % 75) * 4;

    const uint32_t smem_base = smem_u32(dyns);
    const uint32_t xt_base = smem_base + BALL_BYTES;

    // ---------- init: zero XT fully; zero B_all pad cols 100..103 ----------
    {
        uint32_t* xz = (uint32_t*)XT;
        for (int i = tid; i < XT_BYTES / 4; i += 512) xz[i] = 0u;
        for (int i = tid; i < KDIM * 2; i += 512) {
            int row = i >> 1, part = i & 1;
            *(uint32_t*)&Ball[row * BALLS + 100 + part * 2] = 0u;
        }
    }
    __syncthreads();

    // ---------- phase 1: window sums -> XT[ci][f*32 + v] fp16 ----------
    if (lane < 25) {
        const int ciw = warp * 16;
        for (int i = 0; i < 16; ++i) {
            int ci = ciw + i;
            const float* xb = x + ((size_t)(n * CIN + ci)) * CPN + lane;
            int lstart = mf0 - 8; if (lstart < 0) lstart = 0;
            float s = 0.f;
            for (int l = lstart; l < mf0; ++l) s += xb[l * 25];
#pragma unroll
            for (int f = 0; f < 4; ++f) {
                int m = mf0 + f;
                s += xb[m * 25];
                XT[ci * XTS + f * 32 + lane] = __float2half_rn(s);
                if (m >= 8) s -= xb[(m - 8) * 25];
            }
        }
    }
    __syncthreads();

    // ---------- phase 2: B_all[p*256+ci][f*25+w] = XT @ Aw (tensor cores) ----------
    {
        const int mt = warp;   // ci-tile: rows mt*16 .. mt*16+15
        for (int p = 0; p < 3; ++p) {
            uint32_t bb[4][2][2];
#pragma unroll
            for (int nt = 0; nt < 4; ++nt)
#pragma unroll
                for (int k16 = 0; k16 < 2; ++k16)
#pragma unroll
                    for (int j = 0; j < 2; ++j)
                        bb[nt][k16][j] = g_AwFrag2[(((p * 4 + nt) * 2 + k16) * 32 + lane) * 2 + j];

            float ac[4][4][4];
#pragma unroll
            for (int f = 0; f < 4; ++f)
#pragma unroll
                for (int nt = 0; nt < 4; ++nt)
#pragma unroll
                    for (int r = 0; r < 4; ++r) ac[f][nt][r] = 0.f;

#pragma unroll
            for (int f = 0; f < 4; ++f)
#pragma unroll
                for (int k16 = 0; k16 < 2; ++k16) {
                    uint32_t addr = xt_base +
                        ((mt * 16 + (lane & 15)) * XTS + f * 32 + k16 * 16 + (lane >> 4) * 8) * 2;
                    uint32_t a0, a1, a2, a3;
                    LDSM_X4(a0, a1, a2, a3, addr);
#pragma unroll
                    for (int nt = 0; nt < 4; ++nt)
                        mma_f16(ac[f][nt], a0, a1, a2, a3, bb[nt][k16][0], bb[nt][k16][1]);
                }

            const int r0 = p * 256 + mt * 16 + grp;
#pragma unroll
            for (int f = 0; f < 4; ++f) {
#pragma unroll
                for (int nt = 0; nt < 3; ++nt) {
                    int colb = f * 25 + nt * 8 + 2 * tig;
                    Ball[r0 * BALLS + colb] = __float2half_rn(ac[f][nt][0]);
                    Ball[r0 * BALLS + colb + 1] = __float2half_rn(ac[f][nt][1]);
                    Ball[(r0 + 8) * BALLS + colb] = __float2half_rn(ac[f][nt][2]);
                    Ball[(r0 + 8) * BALLS + colb + 1] = __float2half_rn(ac[f][nt][3]);
                }
                if (tig == 0) {
                    Ball[r0 * BALLS + f * 25 + 24] = __float2half_rn(ac[f][3][0]);
                    Ball[(r0 + 8) * BALLS + f * 25 + 24] = __float2half_rn(ac[f][3][2]);
                }
            }
        }
    }
    __syncthreads();

    // ---------- phase 3: main GEMM, A via 4-stage cp.async (in XT region) ----------
    float acc[2][7][4];
#pragma unroll
    for (int i = 0; i < 2; ++i)
#pragma unroll
        for (int j = 0; j < 7; ++j)
#pragma unroll
            for (int r = 0; r < 4; ++r) acc[i][j][r] = 0.f;

    auto load_chunkA = [&](int s, int kc) {
        uint32_t As_b = xt_base + (uint32_t)s * (ASTG * 2);
        const __half* Ag = g_Afrag + (size_t)kc * ASTG;
#pragma unroll
        for (int i = 0; i < 2; ++i) {
            int idx = i * 512 + tid;
            cp16(As_b + idx * 16, Ag + idx * 8);
        }
        asm volatile("cp.async.commit_group;" ::: "memory");
    };

    load_chunkA(0, 0);
    load_chunkA(1, 1);
    load_chunkA(2, 2);
    load_chunkA(3, 3);

    const int matid = lane >> 3;
    const int mrow = lane & 7;
    const int lds_row = (matid & 1) * 8 + mrow;
    const int lds_fn0 = wn * 7 + (matid >> 1);

    for (int it = 0; it < NKC / 2; ++it) {
        if (it < NKC / 2 - 1) asm volatile("cp.async.wait_group 2;" ::: "memory");
        else                  asm volatile("cp.async.wait_group 0;" ::: "memory");
        __syncthreads();

#pragma unroll
        for (int h = 0; h < 2; ++h) {
            const int kc = 2 * it + h;
            const int s = kc & 3;
            const __half* As = (const __half*)((char*)XT + (size_t)s * (ASTG * 2));

#pragma unroll
            for (int k16 = 0; k16 < 2; ++k16) {
                uint4 a0 = *(const uint4*)(As + (((wm * 2 + k16) * 2 + 0) << 8) + lane * 8);
                uint4 a1 = *(const uint4*)(As + (((wm * 2 + k16) * 2 + 1) << 8) + lane * 8);
                uint32_t bfr[16];
                uint32_t baddr = smem_base +
                    ((kc * 32 + k16 * 16 + lds_row) * BALLS + lds_fn0 * 8) * 2;
#pragma unroll
                for (int j = 0; j < 4; ++j) {
                    if (wn == 0 || j < 3)
                        LDSM_X4_T(bfr[4 * j], bfr[4 * j + 1], bfr[4 * j + 2], bfr[4 * j + 3],
                                  baddr + j * 32);
                }
#pragma unroll
                for (int f = 0; f < 7; ++f) {
                    if (f < fnc) {
                        mma_f16(acc[0][f], a0.x, a0.y, a0.z, a0.w, bfr[2 * f], bfr[2 * f + 1]);
                        mma_f16(acc[1][f], a1.x, a1.y, a1.z, a1.w, bfr[2 * f], bfr[2 * f + 1]);
                    }
                }
            }
        }
        __syncthreads();
        if (2 * it + 5 < NKC) {
            load_chunkA((2 * it + 4) & 3, 2 * it + 4);
            load_chunkA((2 * it + 5) & 3, 2 * it + 5);
        }
    }
    __syncthreads();

    // ---------- epilogue: stage z + bias into Cs[e][c] (aliases B_all) ----------
    float* Cs = dyns;
#pragma unroll
    for (int fm = 0; fm < 2; ++fm)
#pragma unroll
        for (int f = 0; f < 7; ++f)
#pragma unroll
            for (int r = 0; r < 4; ++r) {
                int nn = wn * 56 + f * 8 + 2 * tig + (r & 1);
                if (f < fnc && nn < BN) {
                    int c = wm * 32 + fm * 16 + grp + ((r & 2) ? 8 : 0);
                    int g = nn / 25;
                    int w = nn - g * 25;
                    int mf = mf0 + g;
                    float cnt = (float)((mf + 1 < 9) ? (mf + 1) : 9);
                    Cs[nn * CS_STRIDE + c] = acc[fm][f][r] + cnt * g_bias2[c * VV + w];
                }
            }
    __syncthreads();

    // ---------- LN stats ----------
    {
        const int half = tid >> 8;
        const int c = tid & 255;
        float s0 = 0.f, q0 = 0.f, s1 = 0.f, q1 = 0.f;
        const float* c0p = Cs + (half * 2 + 0) * 25 * CS_STRIDE + c;
        const float* c1p = Cs + (half * 2 + 1) * 25 * CS_STRIDE + c;
#pragma unroll
        for (int w = 0; w < 25; ++w) {
            float v0 = c0p[w * CS_STRIDE];
            float v1 = c1p[w * CS_STRIDE];
            s0 += v0; q0 += v0 * v0;
            s1 += v1; q1 += v1 * v1;
        }
#pragma unroll
        for (int off = 16; off > 0; off >>= 1) {
            s0 += __shfl_down_sync(0xffffffffu, s0, off);
            q0 += __shfl_down_sync(0xffffffffu, q0, off);
            s1 += __shfl_down_sync(0xffffffffu, s1, off);
            q1 += __shfl_down_sync(0xffffffffu, q1, off);
        }
        if (lane == 0) {
            red[warp][0] = s0; red[warp][1] = q0;
            red[warp][2] = s1; red[warp][3] = q1;
        }
    }
    __syncthreads();
    if (tid < 4) {
        int hw = (tid >> 1) * 8;
        int sel = (tid & 1) * 2;
        float s = 0.f, q = 0.f;
#pragma unroll
        for (int w = 0; w < 8; ++w) { s += red[hw + w][sel]; q += red[hw + w][sel + 1]; }
        const float inv = 1.f / 6400.f;
        float mean = s * inv;
        float var = q * inv - mean * mean;
        smean[tid] = mean;
        srstd[tid] = rsqrtf(var + 1e-5f);
    }
    __syncthreads();

    // ---------- apply LN + gamma/beta + relu in Cs ----------
    {
        const int half = tid >> 8;
        const int c = tid & 255;
        const float* gm = gamma + c * VV;
        const float* bt = beta + c * VV;
#pragma unroll
        for (int gg = 0; gg < 2; ++gg) {
            int g = half * 2 + gg;
            float mean = smean[g], rstd = srstd[g];
            float* cp = Cs + g * 25 * CS_STRIDE + c;
            for (int w = 0; w < 25; ++w) {
                float z = cp[w * CS_STRIDE];
                float yv = (z - mean) * rstd * gm[w] + bt[w];
                cp[w * CS_STRIDE] = fmaxf(yv, 0.f);
            }
        }
    }
    __syncthreads();

    // ---------- residual + final relu, coalesced float4 ----------
    for (int i = 0; i < 13; ++i) {
        int idx = i * 512 + tid;
        if (idx < 6400) {
            int c = idx / 25;
            int j = idx - c * 25;
            size_t base = ((size_t)(n * CIN + c)) * CPN + loc0 + j * 4;
            float4 xv = *(const float4*)(x + base);
            int e = j * 4;
            float4 yv;
            yv.x = fmaxf(Cs[(e + 0) * CS_STRIDE + c] + xv.x, 0.f);
            yv.y = fmaxf(Cs[(e + 1) * CS_STRIDE + c] + xv.y, 0.f);
            yv.z = fmaxf(Cs[(e + 2) * CS_STRIDE + c] + xv.z, 0.f);
            yv.w = fmaxf(Cs[(e + 3) * CS_STRIDE + c] + xv.w, 0.f);
            *(float4*)(out + base) = yv;
        }
    }
}

// ---------------------------------------------------------------------------
extern "C" void kernel_launch(void* const* d_in, const int* in_sizes, int n_in,
                              void* d_out, int out_size) {
    const float* x      = (const float*)d_in[0];
    const float* A      = (const float*)d_in[1];
    const float* conv_w = (const float*)d_in[2];
    const float* conv_b = (const float*)d_in[3];
    const float* gamma  = (const float*)d_in[4];
    const float* beta   = (const float*)d_in[5];
    const float* ei     = (const float*)d_in[6];
    float* out = (float*)d_out;

    cudaFuncSetAttribute(gemm_kernel, cudaFuncAttributeMaxDynamicSharedMemorySize, GEMM_SMEM);

    prep_kernel<<<(COUT * KDIM + 255) / 256, 256>>>(A, conv_w, conv_b, ei);

    gemm_kernel<<<NCOL / BN, 512, GEMM_SMEM>>>(x, gamma, beta, out);
}

// round 14
// speedup vs baseline: 1.2620x; 1.2620x over previous
#include <cuda_runtime.h>
#include <cuda_fp16.h>
#include <cstdint>

#define NB 16
#define CIN 256
#define LL 300
#define VV 25
#define PP 3
#define COUT 256
#define NCOL 120000
#define CPN 7500
#define KDIM 768

#define BN 100            // 4 LN-frame groups per CTA
#define BALLS 104         // halves per B_all row (208 B, 16B-aligned rows)
#define XTS 136           // halves per XT row (272 B: 16B-aligned, LDSM conflict-free)
#define CS_STRIDE 261
#define BALL_BYTES (KDIM * BALLS * 2)          // 159744
#define XT_BYTES (256 * XTS * 2)               // 69632
#define GEMM_SMEM (BALL_BYTES + XT_BYTES)      // 229376

__device__ __half g_Afrag[COUT * KDIM];         // fp16 fragment-ordered Wall
__device__ uint32_t g_AwFrag2[PP * 4 * 2 * 32 * 2];  // [p][nt][k16][lane][j]
__device__ float g_bias2[COUT * VV];

__device__ __forceinline__ uint32_t smem_u32(const void* p) {
    uint32_t a;
    asm("{ .reg .u64 t; cvta.to.shared.u64 t, %1; cvt.u32.u64 %0, t; }" : "=r"(a) : "l"(p));
    return a;
}
__device__ __forceinline__ void mma_f16(float* d, uint32_t a0, uint32_t a1, uint32_t a2,
                                        uint32_t a3, uint32_t b0, uint32_t b1) {
    asm volatile(
        "mma.sync.aligned.m16n8k16.row.col.f32.f16.f16.f32 "
        "{%0,%1,%2,%3}, {%4,%5,%6,%7}, {%8,%9}, {%0,%1,%2,%3};"
        : "+f"(d[0]), "+f"(d[1]), "+f"(d[2]), "+f"(d[3])
        : "r"(a0), "r"(a1), "r"(a2), "r"(a3), "r"(b0), "r"(b1));
}
#define LDSM_X4_T(r0, r1, r2, r3, addr) \
    asm volatile("ldmatrix.sync.aligned.m8n8.x4.trans.shared.b16 {%0,%1,%2,%3}, [%4];" \
                 : "=r"(r0), "=r"(r1), "=r"(r2), "=r"(r3) : "r"(addr))
#define LDSM_X4(r0, r1, r2, r3, addr) \
    asm volatile("ldmatrix.sync.aligned.m8n8.x4.shared.b16 {%0,%1,%2,%3}, [%4];" \
                 : "=r"(r0), "=r"(r1), "=r"(r2), "=r"(r3) : "r"(addr))

// ---------------- prep: fp16 A fragments, AwFrag2 (per-p B frags), bias2 -----------
__global__ __launch_bounds__(256) void prep_kernel(const float* __restrict__ A,
                                                   const float* __restrict__ conv_w,
                                                   const float* __restrict__ conv_b,
                                                   const float* __restrict__ ei) {
    int e = blockIdx.x * 256 + threadIdx.x;
    if (e < COUT * KDIM) {
        int r = e / KDIM;
        int k = e - r * KDIM;
        int p = k >> 8, ci = k & 255;
        float w = conv_w[((p << 8) + r) * CIN + ci];
        int wm = r >> 5, fm = (r >> 4) & 1, rr = r & 15;
        int kchunk = k >> 5, k16 = (k >> 4) & 1, kkk = k & 15;
        int reg = (rr >> 3) | ((kkk >> 3) << 1);
        int lane = ((rr & 7) << 2) | ((kkk & 7) >> 1);
        int hl = kkk & 1;
        size_t off = ((((size_t)(kchunk * 8 + wm) * 2 + k16) * 2 + fm) * 256)
                     + lane * 8 + reg * 2 + hl;
        g_Afrag[off] = __float2half_rn(w);
    }
    if (e < PP * 4 * 2 * 32 * 2) {
        int j = e & 1;
        int lane = (e >> 1) & 31;
        int k16 = (e >> 6) & 1;
        int nt = (e >> 7) & 3;
        int p = e >> 9;
        int grp = lane >> 2, tig = lane & 3;
        int w = nt * 8 + grp;
        int v = k16 * 16 + j * 8 + 2 * tig;
        float v0 = 0.f, v1 = 0.f;
        if (w < 25) {
            if (v < 25) {
                int a = (p * VV + v) * VV + w;
                v0 = A[a] * ei[a];
            }
            if (v + 1 < 25) {
                int a = (p * VV + v + 1) * VV + w;
                v1 = A[a] * ei[a];
            }
        }
        __half2 h2 = __floats2half2_rn(v0, v1);
        g_AwFrag2[e] = *(uint32_t*)&h2;
    }
    if (e < COUT * VV) {
        int c = e / VV, w = e - (e / VV) * VV;
        float s = 0.f;
        for (int p = 0; p < PP; ++p) {
            float b = conv_b[(p << 8) + c];
            for (int v = 0; v < VV; ++v) {
                int a = (p * VV + v) * VV + w;
                s += b * A[a] * ei[a];
            }
        }
        g_bias2[e] = s;
    }
}

// ---------------- fused mega-kernel: window sums + agg-MMA + GEMM + LN ------------
__global__ __launch_bounds__(512, 1) void gemm_kernel(const float* __restrict__ x,
                                                      const float* __restrict__ gamma,
                                                      const float* __restrict__ beta,
                                                      float* __restrict__ out) {
    extern __shared__ float dyns[];
    __half* Ball = (__half*)dyns;                         // [768][104]
    __half* XT = (__half*)((char*)dyns + BALL_BYTES);     // [256][136]
    __shared__ float red[16][4];
    __shared__ float smean[4], srstd[4];

    const int tid = threadIdx.x;
    const int warp = tid >> 5;
    const int lane = tid & 31;
    const int wm = warp >> 1;
    const int wn = warp & 1;
    const int grp = lane >> 2;
    const int tig = lane & 3;
    const int fnc = wn ? 6 : 7;
    const int bx = blockIdx.x;
    const int n = bx / 75;
    const int loc0 = (bx % 75) * BN;
    const int mf0 = (bx % 75) * 4;

    const uint32_t smem_base = smem_u32(dyns);
    const uint32_t xt_base = smem_base + BALL_BYTES;

    // ---------- init: zero XT fully; zero B_all pad cols 100..103 ----------
    {
        uint32_t* xz = (uint32_t*)XT;
        for (int i = tid; i < XT_BYTES / 4; i += 512) xz[i] = 0u;
        for (int i = tid; i < KDIM * 2; i += 512) {
            int row = i >> 1, part = i & 1;
            *(uint32_t*)&Ball[row * BALLS + 100 + part * 2] = 0u;
        }
    }
    __syncthreads();

    // ---------- phase 1: window sums -> XT[ci][f*32 + v] fp16 (12-MLP loads) -------
    if (lane < 25) {
        const int ciw = warp * 16;
        for (int i = 0; i < 16; ++i) {
            int ci = ciw + i;
            const float* xb = x + ((size_t)(n * CIN + ci)) * CPN + lane;
            float vals[12];
#pragma unroll
            for (int j = 0; j < 12; ++j) {
                int l = mf0 - 8 + j;
                vals[j] = (l >= 0) ? xb[l * 25] : 0.f;
            }
            float s = 0.f;
#pragma unroll
            for (int j = 0; j < 9; ++j) s += vals[j];
            XT[ci * XTS + 0 * 32 + lane] = __float2half_rn(s);
#pragma unroll
            for (int f = 1; f < 4; ++f) {
                s += vals[f + 8] - vals[f - 1];
                XT[ci * XTS + f * 32 + lane] = __float2half_rn(s);
            }
        }
    }
    __syncthreads();

    // ---------- phase 2: B_all[p*256+ci][f*25+w] = XT @ Aw (tensor cores) ----------
    {
        const int mt = warp;
        for (int p = 0; p < 3; ++p) {
            uint32_t bb[4][2][2];
#pragma unroll
            for (int nt = 0; nt < 4; ++nt)
#pragma unroll
                for (int k16 = 0; k16 < 2; ++k16)
#pragma unroll
                    for (int j = 0; j < 2; ++j)
                        bb[nt][k16][j] = g_AwFrag2[(((p * 4 + nt) * 2 + k16) * 32 + lane) * 2 + j];

            float ac[4][4][4];
#pragma unroll
            for (int f = 0; f < 4; ++f)
#pragma unroll
                for (int nt = 0; nt < 4; ++nt)
#pragma unroll
                    for (int r = 0; r < 4; ++r) ac[f][nt][r] = 0.f;

#pragma unroll
            for (int f = 0; f < 4; ++f)
#pragma unroll
                for (int k16 = 0; k16 < 2; ++k16) {
                    uint32_t addr = xt_base +
                        ((mt * 16 + (lane & 15)) * XTS + f * 32 + k16 * 16 + (lane >> 4) * 8) * 2;
                    uint32_t a0, a1, a2, a3;
                    LDSM_X4(a0, a1, a2, a3, addr);
#pragma unroll
                    for (int nt = 0; nt < 4; ++nt)
                        mma_f16(ac[f][nt], a0, a1, a2, a3, bb[nt][k16][0], bb[nt][k16][1]);
                }

            const int r0 = p * 256 + mt * 16 + grp;
#pragma unroll
            for (int f = 0; f < 4; ++f) {
#pragma unroll
                for (int nt = 0; nt < 3; ++nt) {
                    int colb = f * 25 + nt * 8 + 2 * tig;
                    Ball[r0 * BALLS + colb] = __float2half_rn(ac[f][nt][0]);
                    Ball[r0 * BALLS + colb + 1] = __float2half_rn(ac[f][nt][1]);
                    Ball[(r0 + 8) * BALLS + colb] = __float2half_rn(ac[f][nt][2]);
                    Ball[(r0 + 8) * BALLS + colb + 1] = __float2half_rn(ac[f][nt][3]);
                }
                if (tig == 0) {
                    Ball[r0 * BALLS + f * 25 + 24] = __float2half_rn(ac[f][3][0]);
                    Ball[(r0 + 8) * BALLS + f * 25 + 24] = __float2half_rn(ac[f][3][2]);
                }
            }
        }
    }
    __syncthreads();

    // ---------- phase 3: barrier-free mainloop; A from global (regs), B from smem --
    float acc[2][7][4];
#pragma unroll
    for (int i = 0; i < 2; ++i)
#pragma unroll
        for (int j = 0; j < 7; ++j)
#pragma unroll
            for (int r = 0; r < 4; ++r) acc[i][j][r] = 0.f;

    const int matid = lane >> 3;
    const int mrow = lane & 7;
    const int lds_row = (matid & 1) * 8 + mrow;
    const int lds_fn0 = wn * 7 + (matid >> 1);

    auto lda = [&](int g, int fm) -> uint4 {
        return *(const uint4*)(g_Afrag +
            (size_t)(((((g >> 1) * 8 + wm) * 2 + (g & 1)) * 2 + fm) * 256) + lane * 8);
    };
    auto ldb = [&](int g, uint32_t* bf) {
        uint32_t baddr = smem_base + (uint32_t)(((g * 16 + lds_row) * BALLS + lds_fn0 * 8) * 2);
#pragma unroll
        for (int j = 0; j < 4; ++j)
            if (wn == 0 || j < 3)
                LDSM_X4_T(bf[4 * j], bf[4 * j + 1], bf[4 * j + 2], bf[4 * j + 3],
                          baddr + j * 32);
    };
    auto do_mma = [&](const uint4& a0, const uint4& a1, const uint32_t* bf) {
#pragma unroll
        for (int f = 0; f < 7; ++f)
            if (f < fnc) {
                mma_f16(acc[0][f], a0.x, a0.y, a0.z, a0.w, bf[2 * f], bf[2 * f + 1]);
                mma_f16(acc[1][f], a1.x, a1.y, a1.z, a1.w, bf[2 * f], bf[2 * f + 1]);
            }
    };

    uint4 a0c = lda(0, 0), a1c = lda(0, 1);
    uint4 a0n = lda(1, 0), a1n = lda(1, 1);
    uint32_t b0[16], b1[16];
    ldb(0, b0);

#pragma unroll 1
    for (int gg = 0; gg < 24; ++gg) {
        const int g = 2 * gg;
        // even step g: consume (a0c,a1c,b0); prefetch b1 <- g+1, A <- g+2
        ldb(g + 1, b1);
        do_mma(a0c, a1c, b0);
        if (g + 2 < 48) { a0c = lda(g + 2, 0); a1c = lda(g + 2, 1); }
        // odd step g+1: consume (a0n,a1n,b1); prefetch b0 <- g+2, A <- g+3
        if (g + 2 < 48) ldb(g + 2, b0);
        do_mma(a0n, a1n, b1);
        if (g + 3 < 48) { a0n = lda(g + 3, 0); a1n = lda(g + 3, 1); }
    }
    __syncthreads();

    // ---------- epilogue: stage z + bias into Cs[e][c] (aliases B_all) ----------
    float* Cs = dyns;
#pragma unroll
    for (int fm = 0; fm < 2; ++fm)
#pragma unroll
        for (int f = 0; f < 7; ++f)
#pragma unroll
            for (int r = 0; r < 4; ++r) {
                int nn = wn * 56 + f * 8 + 2 * tig + (r & 1);
                if (f < fnc && nn < BN) {
                    int c = wm * 32 + fm * 16 + grp + ((r & 2) ? 8 : 0);
                    int g = nn / 25;
                    int w = nn - g * 25;
                    int mf = mf0 + g;
                    float cnt = (float)((mf + 1 < 9) ? (mf + 1) : 9);
                    Cs[nn * CS_STRIDE + c] = acc[fm][f][r] + cnt * g_bias2[c * VV + w];
                }
            }
    __syncthreads();

    // ---------- LN stats ----------
    {
        const int half = tid >> 8;
        const int c = tid & 255;
        float s0 = 0.f, q0 = 0.f, s1 = 0.f, q1 = 0.f;
        const float* c0p = Cs + (half * 2 + 0) * 25 * CS_STRIDE + c;
        const float* c1p = Cs + (half * 2 + 1) * 25 * CS_STRIDE + c;
#pragma unroll
        for (int w = 0; w < 25; ++w) {
            float v0 = c0p[w * CS_STRIDE];
            float v1 = c1p[w * CS_STRIDE];
            s0 += v0; q0 += v0 * v0;
            s1 += v1; q1 += v1 * v1;
        }
#pragma unroll
        for (int off = 16; off > 0; off >>= 1) {
            s0 += __shfl_down_sync(0xffffffffu, s0, off);
            q0 += __shfl_down_sync(0xffffffffu, q0, off);
            s1 += __shfl_down_sync(0xffffffffu, s1, off);
            q1 += __shfl_down_sync(0xffffffffu, q1, off);
        }
        if (lane == 0) {
            red[warp][0] = s0; red[warp][1] = q0;
            red[warp][2] = s1; red[warp][3] = q1;
        }
    }
    __syncthreads();
    if (tid < 4) {
        int hw = (tid >> 1) * 8;
        int sel = (tid & 1) * 2;
        float s = 0.f, q = 0.f;
#pragma unroll
        for (int w = 0; w < 8; ++w) { s += red[hw + w][sel]; q += red[hw + w][sel + 1]; }
        const float inv = 1.f / 6400.f;
        float mean = s * inv;
        float var = q * inv - mean * mean;
        smean[tid] = mean;
        srstd[tid] = rsqrtf(var + 1e-5f);
    }
    __syncthreads();

    // ---------- apply LN + gamma/beta + relu in Cs ----------
    {
        const int half = tid >> 8;
        const int c = tid & 255;
        const float* gm = gamma + c * VV;
        const float* bt = beta + c * VV;
#pragma unroll
        for (int gg = 0; gg < 2; ++gg) {
            int g = half * 2 + gg;
            float mean = smean[g], rstd = srstd[g];
            float* cp = Cs + g * 25 * CS_STRIDE + c;
            for (int w = 0; w < 25; ++w) {
                float z = cp[w * CS_STRIDE];
                float yv = (z - mean) * rstd * gm[w] + bt[w];
                cp[w * CS_STRIDE] = fmaxf(yv, 0.f);
            }
        }
    }
    __syncthreads();

    // ---------- residual + final relu, coalesced float4 ----------
    for (int i = 0; i < 13; ++i) {
        int idx = i * 512 + tid;
        if (idx < 6400) {
            int c = idx / 25;
            int j = idx - c * 25;
            size_t base = ((size_t)(n * CIN + c)) * CPN + loc0 + j * 4;
            float4 xv = *(const float4*)(x + base);
            int e = j * 4;
            float4 yv;
            yv.x = fmaxf(Cs[(e + 0) * CS_STRIDE + c] + xv.x, 0.f);
            yv.y = fmaxf(Cs[(e + 1) * CS_STRIDE + c] + xv.y, 0.f);
            yv.z = fmaxf(Cs[(e + 2) * CS_STRIDE + c] + xv.z, 0.f);
            yv.w = fmaxf(Cs[(e + 3) * CS_STRIDE + c] + xv.w, 0.f);
            *(float4*)(out + base) = yv;
        }
    }
}

// ---------------------------------------------------------------------------
extern "C" void kernel_launch(void* const* d_in, const int* in_sizes, int n_in,
                              void* d_out, int out_size) {
    const float* x      = (const float*)d_in[0];
    const float* A      = (const float*)d_in[1];
    const float* conv_w = (const float*)d_in[2];
    const float* conv_b = (const float*)d_in[3];
    const float* gamma  = (const float*)d_in[4];
    const float* beta   = (const float*)d_in[5];
    const float* ei     = (const float*)d_in[6];
    float* out = (float*)d_out;

    cudaFuncSetAttribute(gemm_kernel, cudaFuncAttributeMaxDynamicSharedMemorySize, GEMM_SMEM);

    prep_kernel<<<(COUT * KDIM + 255) / 256, 256>>>(A, conv_w, conv_b, ei);

    gemm_kernel<<<NCOL / BN, 512, GEMM_SMEM>>>(x, gamma, beta, out);
}